// round 16
// baseline (speedup 1.0000x reference)
#include <cuda_runtime.h>
#include <math.h>

#define NPTS 8192
#define KNN  10
#define SEG  8
#define SEGLEN (NPTS / SEG)   // 1024

__device__ float4 g_pts[NPTS];
__device__ int    g_nbr[NPTS * KNN];
__device__ float  g_cd[NPTS * SEG * KNN];
__device__ int    g_ci[NPTS * SEG * KNN];
__device__ float4 g_nrm[NPTS];
__device__ float  g_y0[NPTS * 32];
__device__ float  g_y1[NPTS * 64];
__device__ float  g_y2[NPTS * 128];
// stats accumulators: L0 sums [0,32) sq [32,64); L1 [64,128)/[128,192); L2 [192,320)/[320,448)
__device__ double g_acc[448];

// ---------------- LAPACK ssteqr port, all fp32 (matches reference ssyevd) ----------------
__device__ __forceinline__ float fsign_(float a, float b) {
    return b >= 0.0f ? fabsf(a) : -fabsf(a);
}
__device__ __forceinline__ float lapy2f_(float x, float y) {
    float ax = fabsf(x), ay = fabsf(y);
    float w = ax > ay ? ax : ay, z = ax > ay ? ay : ax;
    if (z == 0.0f) return w;
    float q = z / w;
    return w * sqrtf(1.0f + q * q);
}

__device__ void laev2f_(float a, float b, float c,
                        float* rt1, float* rt2, float* cs1, float* sn1) {
    float sm = a + c, df = a - c, adf = fabsf(df);
    float tb = b + b, ab = fabsf(tb);
    float acmx, acmn;
    if (fabsf(a) > fabsf(c)) { acmx = a; acmn = c; } else { acmx = c; acmn = a; }
    float rt;
    if (adf > ab)      { float q = ab / adf; rt = adf * sqrtf(1.0f + q * q); }
    else if (adf < ab) { float q = adf / ab; rt = ab * sqrtf(1.0f + q * q); }
    else               { rt = ab * sqrtf(2.0f); }
    int sgn1;
    if (sm < 0.0f)      { *rt1 = 0.5f * (sm - rt); sgn1 = -1; *rt2 = (acmx / *rt1) * acmn - (b / *rt1) * b; }
    else if (sm > 0.0f) { *rt1 = 0.5f * (sm + rt); sgn1 =  1; *rt2 = (acmx / *rt1) * acmn - (b / *rt1) * b; }
    else                { *rt1 = 0.5f * rt; *rt2 = -0.5f * rt; sgn1 = 1; }
    float cs; int sgn2;
    if (df >= 0.0f) { cs = df + rt; sgn2 = 1; } else { cs = df - rt; sgn2 = -1; }
    float acs = fabsf(cs), c1, s1;
    if (acs > ab) {
        float ct = -tb / cs;
        s1 = 1.0f / sqrtf(1.0f + ct * ct); c1 = ct * s1;
    } else {
        if (ab == 0.0f) { c1 = 1.0f; s1 = 0.0f; }
        else { float tn = -cs / tb; c1 = 1.0f / sqrtf(1.0f + tn * tn); s1 = tn * c1; }
    }
    if (sgn1 == sgn2) { float t = c1; c1 = -s1; s1 = t; }
    *cs1 = c1; *sn1 = s1;
}

__device__ void lartgf_(float f, float g, float* cs, float* sn, float* r) {
    if (g == 0.0f)      { *cs = 1.0f; *sn = 0.0f; *r = f; }
    else if (f == 0.0f) { *cs = 0.0f; *sn = (g >= 0.0f) ? 1.0f : -1.0f; *r = fabsf(g); }
    else {
        float d = sqrtf(f * f + g * g);
        *cs = fabsf(f) / d;
        *r = (f >= 0.0f) ? d : -d;
        *sn = g / *r;
    }
}

__device__ void steqr3f_(float d[3], float e[2], float z[3][3]) {
    const float eps = 5.9604645e-08f;
    const float eps2 = eps * eps;
    const float safmin = 1.17549435e-38f;
    const int n = 3;
    for (int i = 0; i < 3; i++)
        for (int j = 0; j < 3; j++) z[i][j] = (i == j) ? 1.0f : 0.0f;
    int nmaxit = n * 30, jtot = 0, l1 = 1;
    while (1) {
        if (l1 > n) break;
        if (l1 > 1) e[l1 - 2] = 0.0f;
        int m = n;
        for (int mm = l1; mm <= n - 1; mm++) {
            float tst = fabsf(e[mm - 1]);
            if (tst == 0.0f) { m = mm; break; }
            if (tst <= (sqrtf(fabsf(d[mm - 1])) * sqrtf(fabsf(d[mm]))) * eps) {
                e[mm - 1] = 0.0f; m = mm; break;
            }
        }
        int l = l1, lsv = l, lend = m, lendsv = lend;
        l1 = m + 1;
        if (lend == l) continue;
        float anorm = 0.0f;
        for (int i = l; i <= lend; i++) anorm = fmaxf(anorm, fabsf(d[i - 1]));
        for (int i = l; i <  lend; i++) anorm = fmaxf(anorm, fabsf(e[i - 1]));
        if (anorm == 0.0f) continue;
        if (fabsf(d[lend - 1]) < fabsf(d[l - 1])) { lend = lsv; l = lendsv; }
        if (lend > l) {
            for (;;) {   // QL
                if (l != lend) {
                    m = lend;
                    for (int mm = l; mm <= lend - 1; mm++) {
                        float tst = e[mm - 1] * e[mm - 1];
                        if (tst <= (eps2 * fabsf(d[mm - 1])) * fabsf(d[mm]) + safmin) { m = mm; break; }
                    }
                } else m = l;
                if (m < lend) e[m - 1] = 0.0f;
                float p = d[l - 1];
                if (m == l) { d[l - 1] = p; l++; if (l <= lend) continue; break; }
                if (m == l + 1) {
                    float rt1, rt2, c, s;
                    laev2f_(d[l - 1], e[l - 1], d[l], &rt1, &rt2, &c, &s);
                    for (int i = 0; i < 3; i++) {
                        float t = z[i][l];
                        z[i][l]     = c * t - s * z[i][l - 1];
                        z[i][l - 1] = s * t + c * z[i][l - 1];
                    }
                    d[l - 1] = rt1; d[l] = rt2; e[l - 1] = 0.0f;
                    l += 2; if (l <= lend) continue; break;
                }
                if (jtot == nmaxit) break;
                jtot++;
                float g = (d[l] - p) / (2.0f * e[l - 1]);
                float r = lapy2f_(g, 1.0f);
                g = d[m - 1] - p + e[l - 1] / (g + fsign_(r, g));
                float s = 1.0f, c = 1.0f; p = 0.0f;
                float svc[2], svs[2];
                for (int i = m - 1; i >= l; i--) {
                    float f = s * e[i - 1], b = c * e[i - 1];
                    lartgf_(g, f, &c, &s, &r);
                    if (i != m - 1) e[i] = r;
                    g = d[i] - p;
                    r = (d[i - 1] - g) * s + 2.0f * c * b;
                    p = s * r;
                    d[i] = g + p;
                    g = c * r - b;
                    svc[i - 1] = c; svs[i - 1] = -s;
                }
                for (int j = m - 1; j >= l; j--) {
                    float cj = svc[j - 1], sj = svs[j - 1];
                    for (int i = 0; i < 3; i++) {
                        float t = z[i][j];
                        z[i][j]     = cj * t - sj * z[i][j - 1];
                        z[i][j - 1] = sj * t + cj * z[i][j - 1];
                    }
                }
                d[l - 1] -= p; e[l - 1] = g;
            }
        } else {
            for (;;) {   // QR
                if (l != lend) {
                    m = lend;
                    for (int mm = l; mm >= lend + 1; mm--) {
                        float tst = e[mm - 2] * e[mm - 2];
                        if (tst <= (eps2 * fabsf(d[mm - 1])) * fabsf(d[mm - 2]) + safmin) { m = mm; break; }
                    }
                } else m = l;
                if (m > lend) e[m - 2] = 0.0f;
                float p = d[l - 1];
                if (m == l) { d[l - 1] = p; l--; if (l >= lend) continue; break; }
                if (m == l - 1) {
                    float rt1, rt2, c, s;
                    laev2f_(d[l - 2], e[l - 2], d[l - 1], &rt1, &rt2, &c, &s);
                    for (int i = 0; i < 3; i++) {
                        float t = z[i][l - 1];
                        z[i][l - 1] = c * t - s * z[i][l - 2];
                        z[i][l - 2] = s * t + c * z[i][l - 2];
                    }
                    d[l - 2] = rt1; d[l - 1] = rt2; e[l - 2] = 0.0f;
                    l -= 2; if (l >= lend) continue; break;
                }
                if (jtot == nmaxit) break;
                jtot++;
                float g = (d[l - 2] - p) / (2.0f * e[l - 2]);
                float r = lapy2f_(g, 1.0f);
                g = d[m - 1] - p + e[l - 2] / (g + fsign_(r, g));
                float s = 1.0f, c = 1.0f; p = 0.0f;
                float svc[2], svs[2];
                for (int i = m; i <= l - 1; i++) {
                    float f = s * e[i - 1], b = c * e[i - 1];
                    lartgf_(g, f, &c, &s, &r);
                    if (i != m) e[i - 2] = r;
                    g = d[i - 1] - p;
                    r = (d[i] - g) * s + 2.0f * c * b;
                    p = s * r;
                    d[i - 1] = g + p;
                    g = c * r - b;
                    svc[i - 1] = c; svs[i - 1] = s;
                }
                for (int j = m; j <= l - 1; j++) {
                    float cj = svc[j - 1], sj = svs[j - 1];
                    for (int i = 0; i < 3; i++) {
                        float t = z[i][j];
                        z[i][j]     = cj * t - sj * z[i][j - 1];
                        z[i][j - 1] = sj * t + cj * z[i][j - 1];
                    }
                }
                d[l - 1] -= p; e[l - 2] = g;
            }
        }
        if (jtot >= nmaxit) break;
    }
    for (int ii = 2; ii <= 3; ii++) {
        int i = ii - 1, k = i;
        float p = d[i - 1];
        for (int j = ii; j <= 3; j++) if (d[j - 1] < p) { k = j; p = d[j - 1]; }
        if (k != i) {
            d[k - 1] = d[i - 1]; d[i - 1] = p;
            for (int r2 = 0; r2 < 3; r2++) {
                float t = z[r2][i - 1]; z[r2][i - 1] = z[r2][k - 1]; z[r2][k - 1] = t;
            }
        }
    }
}

// BN-apply helper (identical to prior rounds)
__device__ __forceinline__ float bn_relu(float v, int off, int C, int k,
                                         const float* __restrict__ gam,
                                         const float* __restrict__ bet) {
    double m = g_acc[off + k] / (double)NPTS;
    float mean = (float)m;
    float var = (float)(g_acc[off + C + k] / (double)NPTS - m * m);
    float inv = 1.0f / sqrtf(var + 1e-5f);
    return fmaxf(gam[k] * (v - mean) * inv + bet[k], 0.0f);
}

// ---------------- kernels ----------------
// KNN partial scan; 2 candidates per iteration for ONE query (single top-10
// list; insertion order jj then jj+1 == sequential semantics, bit-identical).
// s==0 blocks also zero g_acc (consumed only by downstream gemm kernels).
__global__ void knn_part_kernel(const float* __restrict__ voxels) {
    __shared__ float4 tile[SEGLEN];
    int pb = blockIdx.x / SEG;
    int s  = blockIdx.x % SEG;
    int i  = pb * 256 + threadIdx.x;
    if (s == 0 && pb < 2) {
        int t = pb * 256 + threadIdx.x;
        if (t < 448) g_acc[t] = 0.0;
    }
    for (int t = threadIdx.x; t < SEGLEN; t += 256) {
        int j = s * SEGLEN + t;
        float x = voxels[3 * j], y = voxels[3 * j + 1], z = voxels[3 * j + 2];
        tile[t] = make_float4(x, y, z, x * x + y * y + z * z);
    }
    {
        float x = voxels[3 * i], y = voxels[3 * i + 1], z = voxels[3 * i + 2];
        float4 q = make_float4(x, y, z, x * x + y * y + z * z);
        if (s == 0) g_pts[i] = q;
        __syncthreads();
        float dk[KNN]; int ik[KNN];
#pragma unroll
        for (int k = 0; k < KNN; k++) { dk[k] = 3.4e38f; ik[k] = 0; }
        int jbase = s * SEGLEN;
#pragma unroll 2
        for (int jj = 0; jj < SEGLEN; jj += 2) {
            float4 p0 = tile[jj];
            float4 p1 = tile[jj + 1];
            float dot0 = fmaf(q.x, p0.x, fmaf(q.y, p0.y, q.z * p0.z));
            float dot1 = fmaf(q.x, p1.x, fmaf(q.y, p1.y, q.z * p1.z));
            float d20 = (q.w + p0.w) - 2.0f * dot0;   // identical expr to prior rounds
            float d21 = (q.w + p1.w) - 2.0f * dot1;
            int j0 = jbase + jj;
            if (d20 < dk[KNN - 1] && j0 != i) {
                float cd = d20; int ci = j0;
#pragma unroll
                for (int k = 0; k < KNN; k++) {
                    if (cd < dk[k]) {
                        float td = dk[k]; int ti = ik[k];
                        dk[k] = cd; ik[k] = ci;
                        cd = td; ci = ti;
                    }
                }
            }
            int j1 = j0 + 1;
            if (d21 < dk[KNN - 1] && j1 != i) {
                float cd = d21; int ci = j1;
#pragma unroll
                for (int k = 0; k < KNN; k++) {
                    if (cd < dk[k]) {
                        float td = dk[k]; int ti = ik[k];
                        dk[k] = cd; ik[k] = ci;
                        cd = td; ci = ti;
                    }
                }
            }
        }
        int base = (i * SEG + s) * KNN;
#pragma unroll
        for (int k = 0; k < KNN; k++) { g_cd[base + k] = dk[k]; g_ci[base + k] = ik[k]; }
    }
}

// Merge partial lists (ascending segment order == top_k tie-break) + normals.
__global__ void merge_normals_kernel() {
    int i = blockIdx.x * blockDim.x + threadIdx.x;
    if (i >= NPTS) return;
    float dk[KNN]; int ik[KNN];
#pragma unroll
    for (int k = 0; k < KNN; k++) { dk[k] = 3.4e38f; ik[k] = 0; }
    for (int s = 0; s < SEG; s++) {
        int base = (i * SEG + s) * KNN;
#pragma unroll
        for (int k = 0; k < KNN; k++) {
            float cd = g_cd[base + k];
            if (!(cd < dk[KNN - 1])) break;   // segment list sorted ascending
            int ci = g_ci[base + k];
#pragma unroll
            for (int kk = 0; kk < KNN; kk++) {
                if (cd < dk[kk]) {
                    float td = dk[kk]; int ti = ik[kk];
                    dk[kk] = cd; ik[kk] = ci;
                    cd = td; ci = ti;
                }
            }
        }
    }
#pragma unroll
    for (int k = 0; k < KNN; k++) g_nbr[i * KNN + k] = ik[k];

    // ----- normals (identical numerics to prior rounds) -----
    float4 c = g_pts[i];
    float sxx = 0, sxy = 0, sxz = 0, syy = 0, syz = 0, szz = 0;
    for (int k = 0; k < KNN; k++) {
        float4 p = g_pts[ik[k]];
        float lx = p.x - c.x, ly = p.y - c.y, lz = p.z - c.z;
        sxx += lx * lx; sxy += lx * ly; sxz += lx * lz;
        syy += ly * ly; syz += ly * lz; szz += lz * lz;
    }
    float inv9 = 1.0f / 9.0f;
    float a11 = sxx * inv9, a21 = sxy * inv9, a31 = sxz * inv9;
    float a22 = syy * inv9, a32 = syz * inv9, a33 = szz * inv9;
    float tau = 0.0f, v2 = 0.0f, e0, d1 = a11, d2 = a22, d3 = a33, e1 = a32;
    if (a31 == 0.0f) {
        e0 = a21;
    } else {
        float alpha = a21, xnorm = fabsf(a31);
        float beta = -fsign_(lapy2f_(alpha, xnorm), alpha);
        tau = (beta - alpha) / beta;
        v2 = a31 / (alpha - beta);
        e0 = beta;
        float x1 = tau * (a22 + a32 * v2);
        float x2 = tau * (a32 + a33 * v2);
        float ac = -0.5f * tau * (x1 + x2 * v2);
        float w1 = x1 + ac, w2 = x2 + ac * v2;
        d2 = a22 - 2.0f * w1;
        e1 = a32 - (v2 * w1 + w2);
        d3 = a33 - 2.0f * v2 * w2;
    }
    float dd[3] = {d1, d2, d3};
    float ee[2] = {e0, e1};
    float z[3][3];
    steqr3f_(dd, ee, z);
    if (tau != 0.0f) {
        for (int jc = 0; jc < 3; jc++) {
            float s = tau * (z[1][jc] + v2 * z[2][jc]);
            z[1][jc] -= s;
            z[2][jc] -= s * v2;
        }
    }
    float nx = z[0][0], ny = z[1][0], nz = z[2][0];
    float nrm = sqrtf(nx * nx + ny * ny + nz * nz);
    float inv = 1.0f / fmaxf(nrm, 1e-12f);
    g_nrm[i] = make_float4(nx * inv, ny * inv, nz * inv, 0.0f);
}

// feats + gemm0 (8->32) + stats0.  32 rows x 32 cols per block (1024 thr).
__global__ __launch_bounds__(1024) void gemm0_kernel(const float* __restrict__ W0) {
    __shared__ float sx[32][8];
    __shared__ float sW[256];
    __shared__ double ra[32][32];
    __shared__ double rb[32][32];
    int tid = threadIdx.x;
    int r0 = blockIdx.x * 32;
    if (tid < 256) sW[tid] = W0[tid];
    if (tid < 32) {
        int i = r0 + tid;
        float4 n = g_nrm[i];
        float s = 0.0f;
        for (int k = 0; k < KNN; k++) {
            float4 m = g_nrm[g_nbr[i * KNN + k]];
            float dx = m.x - n.x, dy = m.y - n.y, dz = m.z - n.z;
            s += sqrtf(dx * dx + dy * dy + dz * dz);
        }
        float4 p = g_pts[i];
        sx[tid][0] = p.x; sx[tid][1] = p.y; sx[tid][2] = p.z;
        sx[tid][3] = n.x; sx[tid][4] = n.y; sx[tid][5] = n.z;
        sx[tid][6] = s / (float)KNN;
        sx[tid][7] = sqrtf(p.w);
    }
    __syncthreads();
    int ty = tid >> 5, c = tid & 31;
    float s = 0.0f;
#pragma unroll
    for (int k = 0; k < 8; k++) s = fmaf(sx[ty][k], sW[k * 32 + c], s);
    g_y0[(r0 + ty) * 32 + c] = s;
    ra[ty][c] = (double)s; rb[ty][c] = (double)s * (double)s;
    __syncthreads();
    for (int h = 16; h > 0; h >>= 1) {
        if (ty < h) { ra[ty][c] += ra[ty + h][c]; rb[ty][c] += rb[ty + h][c]; }
        __syncthreads();
    }
    if (ty == 0) { atomicAdd(&g_acc[c], ra[0][c]); atomicAdd(&g_acc[32 + c], rb[0][c]); }
}

// BN0+relu -> gemm1 (32->64) + stats1.  16 rows x 64 cols per block.
__global__ __launch_bounds__(1024) void gemm1_kernel(const float* __restrict__ W1,
                                                     const float* __restrict__ g0,
                                                     const float* __restrict__ b0) {
    __shared__ float sx[16][32];
    __shared__ float sW[2048];
    __shared__ double ra[16][64];
    __shared__ double rb[16][64];
    int tid = threadIdx.x;
    int r0 = blockIdx.x * 16;
    for (int t = tid; t < 2048; t += 1024) sW[t] = W1[t];
    if (tid < 512) {
        int row = tid >> 5, k = tid & 31;
        float v = g_y0[(r0 + row) * 32 + k];
        sx[row][k] = bn_relu(v, 0, 32, k, g0, b0);
    }
    __syncthreads();
    int ty = tid >> 6, c = tid & 63;
    float s = 0.0f;
#pragma unroll
    for (int k = 0; k < 32; k++) s = fmaf(sx[ty][k], sW[k * 64 + c], s);
    g_y1[(r0 + ty) * 64 + c] = s;
    ra[ty][c] = (double)s; rb[ty][c] = (double)s * (double)s;
    __syncthreads();
    for (int h = 8; h > 0; h >>= 1) {
        if (ty < h) { ra[ty][c] += ra[ty + h][c]; rb[ty][c] += rb[ty + h][c]; }
        __syncthreads();
    }
    if (ty == 0) { atomicAdd(&g_acc[64 + c], ra[0][c]); atomicAdd(&g_acc[128 + c], rb[0][c]); }
}

// BN1+relu -> gemm2 (64->128)+bias + stats2.  8 rows x 128 cols per block.
// Reduction buffers ALIAS sW (dead after the FMA loop) to stay under 48KB smem.
__global__ __launch_bounds__(1024) void gemm2_kernel(const float* __restrict__ W2,
                                                     const float* __restrict__ bias2,
                                                     const float* __restrict__ g1,
                                                     const float* __restrict__ b1) {
    __shared__ float sx[8][64];
    __shared__ float sW[8192];   // 32KB; reused as ra/rb (2 x 8KB) after compute
    int tid = threadIdx.x;
    int r0 = blockIdx.x * 8;
    for (int t = tid; t < 8192; t += 1024) sW[t] = W2[t];
    if (tid < 512) {
        int row = tid >> 6, k = tid & 63;
        float v = g_y1[(r0 + row) * 64 + k];
        sx[row][k] = bn_relu(v, 64, 64, k, g1, b1);
    }
    __syncthreads();
    int ty = tid >> 7, c = tid & 127;
    float s = 0.0f;
#pragma unroll
    for (int k = 0; k < 64; k++) s = fmaf(sx[ty][k], sW[k * 128 + c], s);
    s += bias2[c];
    g_y2[(r0 + ty) * 128 + c] = s;
    __syncthreads();                       // all reads of sW done
    double* ra = (double*)sW;              // [8][128]
    double* rb = ra + 1024;                // [8][128]
    ra[ty * 128 + c] = (double)s;
    rb[ty * 128 + c] = (double)s * (double)s;
    __syncthreads();
    for (int h = 4; h > 0; h >>= 1) {
        if (ty < h) {
            ra[ty * 128 + c] += ra[(ty + h) * 128 + c];
            rb[ty * 128 + c] += rb[(ty + h) * 128 + c];
        }
        __syncthreads();
    }
    if (ty == 0) { atomicAdd(&g_acc[192 + c], ra[c]); atomicAdd(&g_acc[320 + c], rb[c]); }
}

__global__ void bnout_kernel(const float* __restrict__ gam, const float* __restrict__ bet,
                             float* __restrict__ out) {
    int idx = blockIdx.x * 256 + threadIdx.x;
    int c = idx & 127;
    double m = g_acc[192 + c] / (double)NPTS;
    float mean = (float)m;
    float var = (float)(g_acc[320 + c] / (double)NPTS - m * m);
    float inv = 1.0f / sqrtf(var + 1e-5f);
    out[idx] = gam[c] * (g_y2[idx] - mean) * inv + bet[c];
}

extern "C" void kernel_launch(void* const* d_in, const int* in_sizes, int n_in,
                              void* d_out, int out_size) {
    const float* voxels = (const float*)d_in[0];
    const float* W0 = (const float*)d_in[1];
    const float* g0 = (const float*)d_in[2];
    const float* b0 = (const float*)d_in[3];
    const float* W1 = (const float*)d_in[4];
    const float* g1 = (const float*)d_in[5];
    const float* b1 = (const float*)d_in[6];
    const float* W2 = (const float*)d_in[7];
    const float* bias2 = (const float*)d_in[8];
    const float* g2 = (const float*)d_in[9];
    const float* b2 = (const float*)d_in[10];
    float* out = (float*)d_out;

    knn_part_kernel<<<(NPTS / 256) * SEG, 256>>>(voxels);
    merge_normals_kernel<<<NPTS / 128, 128>>>();
    gemm0_kernel<<<NPTS / 32, 1024>>>(W0);
    gemm1_kernel<<<NPTS / 16, 1024>>>(W1, g0, b0);
    gemm2_kernel<<<NPTS / 8, 1024>>>(W2, bias2, g1, b1);
    bnout_kernel<<<NPTS * 128 / 256, 256>>>(g2, b2, out);
}

// round 17
// speedup vs baseline: 1.0475x; 1.0475x over previous
#include <cuda_runtime.h>
#include <math.h>

#define NPTS 8192
#define KNN  10
#define SEG  8
#define SEGLEN (NPTS / SEG)   // 1024

__device__ float4 g_pts[NPTS];
__device__ int    g_nbr[NPTS * KNN];
__device__ float  g_cd[NPTS * SEG * KNN];
__device__ int    g_ci[NPTS * SEG * KNN];
__device__ float4 g_nrm[NPTS];
__device__ float  g_y0[NPTS * 32];
__device__ float  g_y1[NPTS * 64];
__device__ float  g_y2[NPTS * 128];
// stats accumulators: L0 sums [0,32) sq [32,64); L1 [64,128)/[128,192); L2 [192,320)/[320,448)
__device__ double g_acc[448];

// ---------------- LAPACK ssteqr port, all fp32 (matches reference ssyevd) ----------------
__device__ __forceinline__ float fsign_(float a, float b) {
    return b >= 0.0f ? fabsf(a) : -fabsf(a);
}
__device__ __forceinline__ float lapy2f_(float x, float y) {
    float ax = fabsf(x), ay = fabsf(y);
    float w = ax > ay ? ax : ay, z = ax > ay ? ay : ax;
    if (z == 0.0f) return w;
    float q = z / w;
    return w * sqrtf(1.0f + q * q);
}

__device__ void laev2f_(float a, float b, float c,
                        float* rt1, float* rt2, float* cs1, float* sn1) {
    float sm = a + c, df = a - c, adf = fabsf(df);
    float tb = b + b, ab = fabsf(tb);
    float acmx, acmn;
    if (fabsf(a) > fabsf(c)) { acmx = a; acmn = c; } else { acmx = c; acmn = a; }
    float rt;
    if (adf > ab)      { float q = ab / adf; rt = adf * sqrtf(1.0f + q * q); }
    else if (adf < ab) { float q = adf / ab; rt = ab * sqrtf(1.0f + q * q); }
    else               { rt = ab * sqrtf(2.0f); }
    int sgn1;
    if (sm < 0.0f)      { *rt1 = 0.5f * (sm - rt); sgn1 = -1; *rt2 = (acmx / *rt1) * acmn - (b / *rt1) * b; }
    else if (sm > 0.0f) { *rt1 = 0.5f * (sm + rt); sgn1 =  1; *rt2 = (acmx / *rt1) * acmn - (b / *rt1) * b; }
    else                { *rt1 = 0.5f * rt; *rt2 = -0.5f * rt; sgn1 = 1; }
    float cs; int sgn2;
    if (df >= 0.0f) { cs = df + rt; sgn2 = 1; } else { cs = df - rt; sgn2 = -1; }
    float acs = fabsf(cs), c1, s1;
    if (acs > ab) {
        float ct = -tb / cs;
        s1 = 1.0f / sqrtf(1.0f + ct * ct); c1 = ct * s1;
    } else {
        if (ab == 0.0f) { c1 = 1.0f; s1 = 0.0f; }
        else { float tn = -cs / tb; c1 = 1.0f / sqrtf(1.0f + tn * tn); s1 = tn * c1; }
    }
    if (sgn1 == sgn2) { float t = c1; c1 = -s1; s1 = t; }
    *cs1 = c1; *sn1 = s1;
}

__device__ void lartgf_(float f, float g, float* cs, float* sn, float* r) {
    if (g == 0.0f)      { *cs = 1.0f; *sn = 0.0f; *r = f; }
    else if (f == 0.0f) { *cs = 0.0f; *sn = (g >= 0.0f) ? 1.0f : -1.0f; *r = fabsf(g); }
    else {
        float d = sqrtf(f * f + g * g);
        *cs = fabsf(f) / d;
        *r = (f >= 0.0f) ? d : -d;
        *sn = g / *r;
    }
}

__device__ void steqr3f_(float d[3], float e[2], float z[3][3]) {
    const float eps = 5.9604645e-08f;
    const float eps2 = eps * eps;
    const float safmin = 1.17549435e-38f;
    const int n = 3;
    for (int i = 0; i < 3; i++)
        for (int j = 0; j < 3; j++) z[i][j] = (i == j) ? 1.0f : 0.0f;
    int nmaxit = n * 30, jtot = 0, l1 = 1;
    while (1) {
        if (l1 > n) break;
        if (l1 > 1) e[l1 - 2] = 0.0f;
        int m = n;
        for (int mm = l1; mm <= n - 1; mm++) {
            float tst = fabsf(e[mm - 1]);
            if (tst == 0.0f) { m = mm; break; }
            if (tst <= (sqrtf(fabsf(d[mm - 1])) * sqrtf(fabsf(d[mm]))) * eps) {
                e[mm - 1] = 0.0f; m = mm; break;
            }
        }
        int l = l1, lsv = l, lend = m, lendsv = lend;
        l1 = m + 1;
        if (lend == l) continue;
        float anorm = 0.0f;
        for (int i = l; i <= lend; i++) anorm = fmaxf(anorm, fabsf(d[i - 1]));
        for (int i = l; i <  lend; i++) anorm = fmaxf(anorm, fabsf(e[i - 1]));
        if (anorm == 0.0f) continue;
        if (fabsf(d[lend - 1]) < fabsf(d[l - 1])) { lend = lsv; l = lendsv; }
        if (lend > l) {
            for (;;) {   // QL
                if (l != lend) {
                    m = lend;
                    for (int mm = l; mm <= lend - 1; mm++) {
                        float tst = e[mm - 1] * e[mm - 1];
                        if (tst <= (eps2 * fabsf(d[mm - 1])) * fabsf(d[mm]) + safmin) { m = mm; break; }
                    }
                } else m = l;
                if (m < lend) e[m - 1] = 0.0f;
                float p = d[l - 1];
                if (m == l) { d[l - 1] = p; l++; if (l <= lend) continue; break; }
                if (m == l + 1) {
                    float rt1, rt2, c, s;
                    laev2f_(d[l - 1], e[l - 1], d[l], &rt1, &rt2, &c, &s);
                    for (int i = 0; i < 3; i++) {
                        float t = z[i][l];
                        z[i][l]     = c * t - s * z[i][l - 1];
                        z[i][l - 1] = s * t + c * z[i][l - 1];
                    }
                    d[l - 1] = rt1; d[l] = rt2; e[l - 1] = 0.0f;
                    l += 2; if (l <= lend) continue; break;
                }
                if (jtot == nmaxit) break;
                jtot++;
                float g = (d[l] - p) / (2.0f * e[l - 1]);
                float r = lapy2f_(g, 1.0f);
                g = d[m - 1] - p + e[l - 1] / (g + fsign_(r, g));
                float s = 1.0f, c = 1.0f; p = 0.0f;
                float svc[2], svs[2];
                for (int i = m - 1; i >= l; i--) {
                    float f = s * e[i - 1], b = c * e[i - 1];
                    lartgf_(g, f, &c, &s, &r);
                    if (i != m - 1) e[i] = r;
                    g = d[i] - p;
                    r = (d[i - 1] - g) * s + 2.0f * c * b;
                    p = s * r;
                    d[i] = g + p;
                    g = c * r - b;
                    svc[i - 1] = c; svs[i - 1] = -s;
                }
                for (int j = m - 1; j >= l; j--) {
                    float cj = svc[j - 1], sj = svs[j - 1];
                    for (int i = 0; i < 3; i++) {
                        float t = z[i][j];
                        z[i][j]     = cj * t - sj * z[i][j - 1];
                        z[i][j - 1] = sj * t + cj * z[i][j - 1];
                    }
                }
                d[l - 1] -= p; e[l - 1] = g;
            }
        } else {
            for (;;) {   // QR
                if (l != lend) {
                    m = lend;
                    for (int mm = l; mm >= lend + 1; mm--) {
                        float tst = e[mm - 2] * e[mm - 2];
                        if (tst <= (eps2 * fabsf(d[mm - 1])) * fabsf(d[mm - 2]) + safmin) { m = mm; break; }
                    }
                } else m = l;
                if (m > lend) e[m - 2] = 0.0f;
                float p = d[l - 1];
                if (m == l) { d[l - 1] = p; l--; if (l >= lend) continue; break; }
                if (m == l - 1) {
                    float rt1, rt2, c, s;
                    laev2f_(d[l - 2], e[l - 2], d[l - 1], &rt1, &rt2, &c, &s);
                    for (int i = 0; i < 3; i++) {
                        float t = z[i][l - 1];
                        z[i][l - 1] = c * t - s * z[i][l - 2];
                        z[i][l - 2] = s * t + c * z[i][l - 2];
                    }
                    d[l - 2] = rt1; d[l - 1] = rt2; e[l - 2] = 0.0f;
                    l -= 2; if (l >= lend) continue; break;
                }
                if (jtot == nmaxit) break;
                jtot++;
                float g = (d[l - 2] - p) / (2.0f * e[l - 2]);
                float r = lapy2f_(g, 1.0f);
                g = d[m - 1] - p + e[l - 2] / (g + fsign_(r, g));
                float s = 1.0f, c = 1.0f; p = 0.0f;
                float svc[2], svs[2];
                for (int i = m; i <= l - 1; i++) {
                    float f = s * e[i - 1], b = c * e[i - 1];
                    lartgf_(g, f, &c, &s, &r);
                    if (i != m) e[i - 2] = r;
                    g = d[i - 1] - p;
                    r = (d[i] - g) * s + 2.0f * c * b;
                    p = s * r;
                    d[i - 1] = g + p;
                    g = c * r - b;
                    svc[i - 1] = c; svs[i - 1] = s;
                }
                for (int j = m; j <= l - 1; j++) {
                    float cj = svc[j - 1], sj = svs[j - 1];
                    for (int i = 0; i < 3; i++) {
                        float t = z[i][j];
                        z[i][j]     = cj * t - sj * z[i][j - 1];
                        z[i][j - 1] = sj * t + cj * z[i][j - 1];
                    }
                }
                d[l - 1] -= p; e[l - 2] = g;
            }
        }
        if (jtot >= nmaxit) break;
    }
    for (int ii = 2; ii <= 3; ii++) {
        int i = ii - 1, k = i;
        float p = d[i - 1];
        for (int j = ii; j <= 3; j++) if (d[j - 1] < p) { k = j; p = d[j - 1]; }
        if (k != i) {
            d[k - 1] = d[i - 1]; d[i - 1] = p;
            for (int r2 = 0; r2 < 3; r2++) {
                float t = z[r2][i - 1]; z[r2][i - 1] = z[r2][k - 1]; z[r2][k - 1] = t;
            }
        }
    }
}

// BN-apply helper (identical to prior rounds)
__device__ __forceinline__ float bn_relu(float v, int off, int C, int k,
                                         const float* __restrict__ gam,
                                         const float* __restrict__ bet) {
    double m = g_acc[off + k] / (double)NPTS;
    float mean = (float)m;
    float var = (float)(g_acc[off + C + k] / (double)NPTS - m * m);
    float inv = 1.0f / sqrtf(var + 1e-5f);
    return fmaxf(gam[k] * (v - mean) * inv + bet[k], 0.0f);
}

// ---------------- kernels ----------------
// KNN partial scan (validated best); s==0 blocks zero g_acc.
__global__ void knn_part_kernel(const float* __restrict__ voxels) {
    __shared__ float4 tile[SEGLEN];
    int pb = blockIdx.x / SEG;
    int s  = blockIdx.x % SEG;
    int i  = pb * 256 + threadIdx.x;
    if (s == 0 && pb < 2) {
        int t = pb * 256 + threadIdx.x;
        if (t < 448) g_acc[t] = 0.0;
    }
    for (int t = threadIdx.x; t < SEGLEN; t += 256) {
        int j = s * SEGLEN + t;
        float x = voxels[3 * j], y = voxels[3 * j + 1], z = voxels[3 * j + 2];
        tile[t] = make_float4(x, y, z, x * x + y * y + z * z);
    }
    {
        float x = voxels[3 * i], y = voxels[3 * i + 1], z = voxels[3 * i + 2];
        float4 q = make_float4(x, y, z, x * x + y * y + z * z);
        if (s == 0) g_pts[i] = q;
        __syncthreads();
        float dk[KNN]; int ik[KNN];
#pragma unroll
        for (int k = 0; k < KNN; k++) { dk[k] = 3.4e38f; ik[k] = 0; }
        int jbase = s * SEGLEN;
#pragma unroll 4
        for (int jj = 0; jj < SEGLEN; jj++) {
            float4 p = tile[jj];
            float dot = fmaf(q.x, p.x, fmaf(q.y, p.y, q.z * p.z));
            float d2 = (q.w + p.w) - 2.0f * dot;
            int j = jbase + jj;
            if (d2 < dk[KNN - 1] && j != i) {
                float cd = d2; int ci = j;
#pragma unroll
                for (int k = 0; k < KNN; k++) {
                    if (cd < dk[k]) {
                        float td = dk[k]; int ti = ik[k];
                        dk[k] = cd; ik[k] = ci;
                        cd = td; ci = ti;
                    }
                }
            }
        }
        int base = (i * SEG + s) * KNN;
#pragma unroll
        for (int k = 0; k < KNN; k++) { g_cd[base + k] = dk[k]; g_ci[base + k] = ik[k]; }
    }
}

// Merge partial lists (ascending segment order == top_k tie-break) + normals.
__global__ void merge_normals_kernel() {
    int i = blockIdx.x * blockDim.x + threadIdx.x;
    if (i >= NPTS) return;
    float dk[KNN]; int ik[KNN];
#pragma unroll
    for (int k = 0; k < KNN; k++) { dk[k] = 3.4e38f; ik[k] = 0; }
    for (int s = 0; s < SEG; s++) {
        int base = (i * SEG + s) * KNN;
#pragma unroll
        for (int k = 0; k < KNN; k++) {
            float cd = g_cd[base + k];
            if (!(cd < dk[KNN - 1])) break;
            int ci = g_ci[base + k];
#pragma unroll
            for (int kk = 0; kk < KNN; kk++) {
                if (cd < dk[kk]) {
                    float td = dk[kk]; int ti = ik[kk];
                    dk[kk] = cd; ik[kk] = ci;
                    cd = td; ci = ti;
                }
            }
        }
    }
#pragma unroll
    for (int k = 0; k < KNN; k++) g_nbr[i * KNN + k] = ik[k];

    // ----- normals (identical numerics to prior rounds) -----
    float4 c = g_pts[i];
    float sxx = 0, sxy = 0, sxz = 0, syy = 0, syz = 0, szz = 0;
    for (int k = 0; k < KNN; k++) {
        float4 p = g_pts[ik[k]];
        float lx = p.x - c.x, ly = p.y - c.y, lz = p.z - c.z;
        sxx += lx * lx; sxy += lx * ly; sxz += lx * lz;
        syy += ly * ly; syz += ly * lz; szz += lz * lz;
    }
    float inv9 = 1.0f / 9.0f;
    float a11 = sxx * inv9, a21 = sxy * inv9, a31 = sxz * inv9;
    float a22 = syy * inv9, a32 = syz * inv9, a33 = szz * inv9;
    float tau = 0.0f, v2 = 0.0f, e0, d1 = a11, d2 = a22, d3 = a33, e1 = a32;
    if (a31 == 0.0f) {
        e0 = a21;
    } else {
        float alpha = a21, xnorm = fabsf(a31);
        float beta = -fsign_(lapy2f_(alpha, xnorm), alpha);
        tau = (beta - alpha) / beta;
        v2 = a31 / (alpha - beta);
        e0 = beta;
        float x1 = tau * (a22 + a32 * v2);
        float x2 = tau * (a32 + a33 * v2);
        float ac = -0.5f * tau * (x1 + x2 * v2);
        float w1 = x1 + ac, w2 = x2 + ac * v2;
        d2 = a22 - 2.0f * w1;
        e1 = a32 - (v2 * w1 + w2);
        d3 = a33 - 2.0f * v2 * w2;
    }
    float dd[3] = {d1, d2, d3};
    float ee[2] = {e0, e1};
    float z[3][3];
    steqr3f_(dd, ee, z);
    if (tau != 0.0f) {
        for (int jc = 0; jc < 3; jc++) {
            float s = tau * (z[1][jc] + v2 * z[2][jc]);
            z[1][jc] -= s;
            z[2][jc] -= s * v2;
        }
    }
    float nx = z[0][0], ny = z[1][0], nz = z[2][0];
    float nrm = sqrtf(nx * nx + ny * ny + nz * nz);
    float inv = 1.0f / fmaxf(nrm, 1e-12f);
    g_nrm[i] = make_float4(nx * inv, ny * inv, nz * inv, 0.0f);
}

// feats + gemm0 (8->32) + stats0.  32 rows/block; feats gather parallelized
// over 320 threads (term order preserved -> bit-identical row sums).
__global__ __launch_bounds__(1024) void gemm0_kernel(const float* __restrict__ W0) {
    __shared__ float sx[32][8];
    __shared__ float st[32][KNN];
    __shared__ float sW[256];
    __shared__ double ra[32][32];
    __shared__ double rb[32][32];
    int tid = threadIdx.x;
    int r0 = blockIdx.x * 32;
    if (tid < 256) sW[tid] = W0[tid];
    if (tid < 32 * KNN) {
        int row = tid / KNN, k = tid % KNN;
        int i = r0 + row;
        float4 n = g_nrm[i];
        float4 m = g_nrm[g_nbr[i * KNN + k]];
        float dx = m.x - n.x, dy = m.y - n.y, dz = m.z - n.z;
        st[row][k] = sqrtf(dx * dx + dy * dy + dz * dz);
    }
    __syncthreads();
    if (tid < 32) {
        int i = r0 + tid;
        float s = 0.0f;
#pragma unroll
        for (int k = 0; k < KNN; k++) s += st[tid][k];   // same k order as before
        float4 n = g_nrm[i];
        float4 p = g_pts[i];
        sx[tid][0] = p.x; sx[tid][1] = p.y; sx[tid][2] = p.z;
        sx[tid][3] = n.x; sx[tid][4] = n.y; sx[tid][5] = n.z;
        sx[tid][6] = s / (float)KNN;
        sx[tid][7] = sqrtf(p.w);
    }
    __syncthreads();
    int ty = tid >> 5, c = tid & 31;
    float s = 0.0f;
#pragma unroll
    for (int k = 0; k < 8; k++) s = fmaf(sx[ty][k], sW[k * 32 + c], s);
    g_y0[(r0 + ty) * 32 + c] = s;
    ra[ty][c] = (double)s; rb[ty][c] = (double)s * (double)s;
    __syncthreads();
    for (int h = 16; h > 0; h >>= 1) {
        if (ty < h) { ra[ty][c] += ra[ty + h][c]; rb[ty][c] += rb[ty + h][c]; }
        __syncthreads();
    }
    if (ty == 0) { atomicAdd(&g_acc[c], ra[0][c]); atomicAdd(&g_acc[32 + c], rb[0][c]); }
}

// BN0+relu -> gemm1 (32->64) + stats1.  32 rows/block, 2 rows per thread
// sharing one sW load (per-output FMA chain unchanged -> bit-identical).
__global__ __launch_bounds__(1024) void gemm1_kernel(const float* __restrict__ W1,
                                                     const float* __restrict__ g0,
                                                     const float* __restrict__ b0) {
    __shared__ float sx[32][32];
    __shared__ float sW[2048];
    __shared__ double ra[16][64];
    __shared__ double rb[16][64];
    int tid = threadIdx.x;
    int r0 = blockIdx.x * 32;
    for (int t = tid; t < 2048; t += 1024) sW[t] = W1[t];
    {
        int row = tid >> 5, k = tid & 31;   // 1024 threads cover 32x32
        float v = g_y0[(r0 + row) * 32 + k];
        sx[row][k] = bn_relu(v, 0, 32, k, g0, b0);
    }
    __syncthreads();
    int ty = tid >> 6, c = tid & 63;        // ty 0..15
    float sa = 0.0f, sb = 0.0f;
#pragma unroll
    for (int k = 0; k < 32; k++) {
        float w = sW[k * 64 + c];
        sa = fmaf(sx[ty][k], w, sa);
        sb = fmaf(sx[ty + 16][k], w, sb);
    }
    g_y1[(r0 + ty) * 64 + c] = sa;
    g_y1[(r0 + ty + 16) * 64 + c] = sb;
    ra[ty][c] = (double)sa + (double)sb;
    rb[ty][c] = (double)sa * (double)sa + (double)sb * (double)sb;
    __syncthreads();
    for (int h = 8; h > 0; h >>= 1) {
        if (ty < h) { ra[ty][c] += ra[ty + h][c]; rb[ty][c] += rb[ty + h][c]; }
        __syncthreads();
    }
    if (ty == 0) { atomicAdd(&g_acc[64 + c], ra[0][c]); atomicAdd(&g_acc[128 + c], rb[0][c]); }
}

// BN1+relu -> gemm2 (64->128)+bias + stats2.  16 rows/block, 2 rows/thread.
// Reduction buffers ALIAS sW (dead after the FMA loop).
__global__ __launch_bounds__(1024) void gemm2_kernel(const float* __restrict__ W2,
                                                     const float* __restrict__ bias2,
                                                     const float* __restrict__ g1,
                                                     const float* __restrict__ b1) {
    __shared__ float sx[16][64];
    __shared__ float sW[8192];   // 32KB; reused as ra/rb (2 x 8KB) after compute
    int tid = threadIdx.x;
    int r0 = blockIdx.x * 16;
    for (int t = tid; t < 8192; t += 1024) sW[t] = W2[t];
    {
        int row = tid >> 6, k = tid & 63;   // 1024 threads cover 16x64
        float v = g_y1[(r0 + row) * 64 + k];
        sx[row][k] = bn_relu(v, 64, 64, k, g1, b1);
    }
    __syncthreads();
    int ty = tid >> 7, c = tid & 127;       // ty 0..7
    float sa = 0.0f, sb = 0.0f;
#pragma unroll
    for (int k = 0; k < 64; k++) {
        float w = sW[k * 128 + c];
        sa = fmaf(sx[ty][k], w, sa);
        sb = fmaf(sx[ty + 8][k], w, sb);
    }
    sa += bias2[c];
    sb += bias2[c];
    g_y2[(r0 + ty) * 128 + c] = sa;
    g_y2[(r0 + ty + 8) * 128 + c] = sb;
    __syncthreads();                       // all reads of sW done
    double* ra = (double*)sW;              // [8][128]
    double* rb = ra + 1024;                // [8][128]
    ra[ty * 128 + c] = (double)sa + (double)sb;
    rb[ty * 128 + c] = (double)sa * (double)sa + (double)sb * (double)sb;
    __syncthreads();
    for (int h = 4; h > 0; h >>= 1) {
        if (ty < h) {
            ra[ty * 128 + c] += ra[(ty + h) * 128 + c];
            rb[ty * 128 + c] += rb[(ty + h) * 128 + c];
        }
        __syncthreads();
    }
    if (ty == 0) { atomicAdd(&g_acc[192 + c], ra[c]); atomicAdd(&g_acc[320 + c], rb[c]); }
}

__global__ void bnout_kernel(const float* __restrict__ gam, const float* __restrict__ bet,
                             float* __restrict__ out) {
    int idx = blockIdx.x * 256 + threadIdx.x;
    int c = idx & 127;
    double m = g_acc[192 + c] / (double)NPTS;
    float mean = (float)m;
    float var = (float)(g_acc[320 + c] / (double)NPTS - m * m);
    float inv = 1.0f / sqrtf(var + 1e-5f);
    out[idx] = gam[c] * (g_y2[idx] - mean) * inv + bet[c];
}

extern "C" void kernel_launch(void* const* d_in, const int* in_sizes, int n_in,
                              void* d_out, int out_size) {
    const float* voxels = (const float*)d_in[0];
    const float* W0 = (const float*)d_in[1];
    const float* g0 = (const float*)d_in[2];
    const float* b0 = (const float*)d_in[3];
    const float* W1 = (const float*)d_in[4];
    const float* g1 = (const float*)d_in[5];
    const float* b1 = (const float*)d_in[6];
    const float* W2 = (const float*)d_in[7];
    const float* bias2 = (const float*)d_in[8];
    const float* g2 = (const float*)d_in[9];
    const float* b2 = (const float*)d_in[10];
    float* out = (float*)d_out;

    knn_part_kernel<<<(NPTS / 256) * SEG, 256>>>(voxels);
    merge_normals_kernel<<<NPTS / 128, 128>>>();
    gemm0_kernel<<<NPTS / 32, 1024>>>(W0);
    gemm1_kernel<<<NPTS / 32, 1024>>>(W1, g0, b0);
    gemm2_kernel<<<NPTS / 16, 1024>>>(W2, bias2, g1, b1);
    bnout_kernel<<<NPTS * 128 / 256, 256>>>(g2, b2, out);
}